// round 8
// baseline (speedup 1.0000x reference)
#include <cuda_runtime.h>
#include <cuda_bf16.h>
#include <cstdint>

// ---------------------------------------------------------------------------
// Mamba layer. R7: 3-stage GEMM pipeline, fused prep kernel, combine folded
// into scan pass 1.  (HMMA bf16x3 GEMMs + 8-chunk parallel scan.)
//   B=4, L=1024, D_MODEL=512, D_INNER=1024, D_STATE=16, D_CONV=4
// ---------------------------------------------------------------------------

typedef __nv_bfloat16 bf16;

#define NB      4
#define NL      1024
#define DM      512
#define DI      1024
#define DS      16
#define M_ROWS  (NB*NL)          // 4096
#define NC2     1152             // padded: 1024 delta | 16 B | 16 C | 96 pad
#define TQ      16               // scan tile (timesteps)
#define NCH     8                // scan chunks
#define CHL     (NL/NCH)         // 128 steps per chunk

// fp32 scratch
__device__ float g_xr  [M_ROWS * 2048];
__device__ float g_xc  [M_ROWS * DI];
__device__ float g_gate[M_ROWS * DI];
__device__ float g_dbc [M_ROWS * NC2];
__device__ float g_o   [M_ROWS * DM];
__device__ float g_bc  [NC2];

// chunked-scan state: [chunk][b][i][s] flattened
#define CHST (NB * DI * DS)      // 65536 per chunk
__device__ float g_hl [NCH * CHST];
__device__ float g_ap [NCH * CHST];

// bf16 hi/lo operand scratch
__device__ bf16 g_xhi [M_ROWS * DM],   g_xlo [M_ROWS * DM];    // clip(x)
__device__ bf16 g_xchi[M_ROWS * DI],   g_xclo[M_ROWS * DI];    // xc
__device__ bf16 g_yghi[M_ROWS * DI],   g_yglo[M_ROWS * DI];    // yg
__device__ bf16 g_w1hi[2048 * DM],     g_w1lo[2048 * DM];      // W_in^T  [2048,512]
__device__ bf16 g_w3hi[NC2 * DI],      g_w3lo[NC2 * DI];       // Wcomb^T [1152,1024]
__device__ bf16 g_w4hi[DM * DI],       g_w4lo[DM * DI];        // W_out^T [512,1024]

// ---------------------------------------------------------------------------
// helpers
// ---------------------------------------------------------------------------
__device__ __forceinline__ uint32_t s2u(const void* p) {
    uint32_t a;
    asm("{ .reg .u64 t; cvta.to.shared.u64 t, %1; cvt.u32.u64 %0, t; }"
        : "=r"(a) : "l"(p));
    return a;
}

__device__ __forceinline__ void cp16(uint32_t dst, const void* src) {
    asm volatile("cp.async.cg.shared.global [%0], [%1], 16;"
                 :: "r"(dst), "l"(src));
}
__device__ __forceinline__ void cp_commit() {
    asm volatile("cp.async.commit_group;");
}
template<int N> __device__ __forceinline__ void cp_wait() {
    asm volatile("cp.async.wait_group %0;" :: "n"(N));
}

__device__ __forceinline__ void ldmx4(uint32_t* r, uint32_t addr) {
    asm volatile("ldmatrix.sync.aligned.m8n8.x4.shared.b16 {%0,%1,%2,%3}, [%4];"
                 : "=r"(r[0]), "=r"(r[1]), "=r"(r[2]), "=r"(r[3]) : "r"(addr));
}

__device__ __forceinline__ void mma16816(float* c, const uint32_t* a,
                                         uint32_t b0, uint32_t b1) {
    asm volatile(
        "mma.sync.aligned.m16n8k16.row.col.f32.bf16.bf16.f32 "
        "{%0,%1,%2,%3}, {%4,%5,%6,%7}, {%8,%9}, {%0,%1,%2,%3};"
        : "+f"(c[0]), "+f"(c[1]), "+f"(c[2]), "+f"(c[3])
        : "r"(a[0]), "r"(a[1]), "r"(a[2]), "r"(a[3]), "r"(b0), "r"(b1));
}

__device__ __forceinline__ void split32(float v, bf16* phi, bf16* plo) {
    bf16 h = __float2bfloat16(v);
    *phi = h;
    *plo = __float2bfloat16(v - __bfloat162float(h));
}

// ---------------------------------------------------------------------------
// bf16x3 MMA GEMM: C[M,N] = A * B^T (+ bias), fp32 accumulate.
//   CTA 128x128, BK=32, 8 warps (2x4), warp tile 64x32, 3-stage cp.async.
//   Smem rows padded to 40 bf16 (80B): conflict-free ldmatrix.
// ---------------------------------------------------------------------------
#define APITCH      40
#define MAT_BYTES   (128 * APITCH * 2)        // 10240
#define STAGE_BYTES (4 * MAT_BYTES)           // 40960
#define NSTAGE      3
#define GEMM_SMEM   (NSTAGE * STAGE_BYTES)    // 122880

__device__ __forceinline__ void load_mat(const bf16* __restrict__ g,
                                         int base_row, int K, int k0,
                                         uint32_t dst, int tid) {
    #pragma unroll
    for (int it = 0; it < 2; ++it) {
        int j = tid + it * 256;                 // 0..511
        int r = j >> 2;                         // 0..127
        int c = j & 3;                          // 16B chunk
        cp16(dst + r * 80 + c * 16,
             g + (size_t)(base_row + r) * K + k0 + c * 8);
    }
}

__device__ __forceinline__ void load_chunk(const bf16* __restrict__ Ahi,
                                           const bf16* __restrict__ Alo,
                                           const bf16* __restrict__ Bhi,
                                           const bf16* __restrict__ Blo,
                                           int row0, int col0, int K, int k0,
                                           uint32_t st, int tid) {
    load_mat(Ahi, row0, K, k0, st + 0*MAT_BYTES, tid);
    load_mat(Alo, row0, K, k0, st + 1*MAT_BYTES, tid);
    load_mat(Bhi, col0, K, k0, st + 2*MAT_BYTES, tid);
    load_mat(Blo, col0, K, k0, st + 3*MAT_BYTES, tid);
}

template<bool BIAS>
__global__ __launch_bounds__(256)
void mmagemm_kernel(const bf16* __restrict__ Ahi, const bf16* __restrict__ Alo,
                    const bf16* __restrict__ Bhi, const bf16* __restrict__ Blo,
                    const float* __restrict__ bias, float* __restrict__ C,
                    int K, int ldc)
{
    extern __shared__ char smem[];
    const uint32_t sb = s2u(smem);
    const int tid  = threadIdx.x;
    const int wid  = tid >> 5;
    const int lane = tid & 31;
    const int row0 = blockIdx.y * 128;
    const int col0 = blockIdx.x * 128;
    const int row_w = (wid & 1) * 64;
    const int col_w = (wid >> 1) * 32;

    float acc[4][4][4] = {};

    const int nchunk = K >> 5;

    // prologue: chunks 0,1 -> stages 0,1
    load_chunk(Ahi, Alo, Bhi, Blo, row0, col0, K, 0, sb, tid);
    cp_commit();
    load_chunk(Ahi, Alo, Bhi, Blo, row0, col0, K, 32, sb + STAGE_BYTES, tid);
    cp_commit();

    const int lrow = lane & 15;
    const int lhal = (lane >> 4) & 1;

    int stage = 0, nstage = 2 % NSTAGE;
    for (int i = 0; i < nchunk; ++i) {
        if (i + 2 < nchunk) {
            load_chunk(Ahi, Alo, Bhi, Blo, row0, col0, K, (i + 2) * 32,
                       sb + (uint32_t)nstage * STAGE_BYTES, tid);
            cp_commit();
            cp_wait<2>();
        } else if (i + 1 < nchunk) {
            cp_wait<1>();
        } else {
            cp_wait<0>();
        }
        __syncthreads();

        const uint32_t st = sb + (uint32_t)stage * STAGE_BYTES;
        #pragma unroll
        for (int ks = 0; ks < 2; ++ks) {
            uint32_t ah[4][4], al[4][4], bh[2][4], bl[2][4];
            const uint32_t koff = ks * 32 + lhal * 16;
            #pragma unroll
            for (int mb = 0; mb < 4; ++mb) {
                const uint32_t ra = (row_w + mb * 16 + lrow) * 80 + koff;
                ldmx4(ah[mb], st + 0*MAT_BYTES + ra);
                ldmx4(al[mb], st + 1*MAT_BYTES + ra);
            }
            #pragma unroll
            for (int nb2 = 0; nb2 < 2; ++nb2) {
                const uint32_t rb = (col_w + nb2 * 16 + lrow) * 80 + koff;
                ldmx4(bh[nb2], st + 2*MAT_BYTES + rb);
                ldmx4(bl[nb2], st + 3*MAT_BYTES + rb);
            }
            #pragma unroll
            for (int mb = 0; mb < 4; ++mb) {
                #pragma unroll
                for (int nb2 = 0; nb2 < 2; ++nb2) {
                    #pragma unroll
                    for (int hf = 0; hf < 2; ++hf) {
                        float* c = acc[mb][nb2 * 2 + hf];
                        mma16816(c, ah[mb], bh[nb2][hf], bh[nb2][hf + 2]);
                        mma16816(c, ah[mb], bl[nb2][hf], bl[nb2][hf + 2]);
                        mma16816(c, al[mb], bh[nb2][hf], bh[nb2][hf + 2]);
                    }
                }
            }
        }
        __syncthreads();
        stage  = (stage  + 1 == NSTAGE) ? 0 : stage  + 1;
        nstage = (nstage + 1 == NSTAGE) ? 0 : nstage + 1;
    }

    const int g   = lane >> 2;
    const int tig = lane & 3;
    #pragma unroll
    for (int mb = 0; mb < 4; ++mb) {
        #pragma unroll
        for (int nb = 0; nb < 4; ++nb) {
            const int col = col0 + col_w + nb * 8 + tig * 2;
            const int r0  = row0 + row_w + mb * 16 + g;
            float* c = acc[mb][nb];
            float2 v0 = make_float2(c[0], c[1]);
            float2 v1 = make_float2(c[2], c[3]);
            if (BIAS) {
                const float b0 = bias[col], b1 = bias[col + 1];
                v0.x += b0; v0.y += b1;
                v1.x += b0; v1.y += b1;
            }
            *(float2*)&C[(size_t)r0 * ldc + col]       = v0;
            *(float2*)&C[(size_t)(r0 + 8) * ldc + col] = v1;
        }
    }
}

// ---------------------------------------------------------------------------
// fused prep kernel: one launch, segmented grid; all segments run in parallel.
//   S0 [0,8192):     clip(x) -> bf16 hi/lo
//   S1 [+1024):      W_in  transpose+split -> w1   (K=512,  N=2048)
//   S2 [+1024):      W_dt  transpose+split -> w3   (K=1024, N=1024, ro=0)
//   S3 [+32):        W_x   transpose+split -> w3   (K=1024, N=32,  ro=1024)
//   S4 [+512):       W_out transpose+split -> w4   (K=1024, N=512)
//   S5 [+384):       zero-pad w3 rows [1056,1152)
//   S6 [+5):         combined bias [b_dt | 0]
// ---------------------------------------------------------------------------
#define PREP_BLOCKS (8192 + 1024 + 1024 + 32 + 512 + 384 + 5)

__global__ __launch_bounds__(256)
void prep_kernel(const float* __restrict__ x,
                 const float* __restrict__ W_in,
                 const float* __restrict__ W_dt,
                 const float* __restrict__ W_x,
                 const float* __restrict__ W_out,
                 const float* __restrict__ b_dt)
{
    __shared__ float t[32][33];
    int bid = blockIdx.x;
    const int tid = threadIdx.x;

    if (bid < 8192) {                       // S0: split x
        int idx = bid * 256 + tid;
        float v = fminf(fmaxf(x[idx], -10.f), 10.f);
        split32(v, &g_xhi[idx], &g_xlo[idx]);
        return;
    }
    bid -= 8192;

    const float* src; bf16 *dhi, *dlo;
    int N, ldk, ro;
    if (bid < 1024)      { src = W_in;  N = 2048; dhi = g_w1hi; dlo = g_w1lo; ldk = 512;  ro = 0; }
    else if (bid < 2048) { bid -= 1024; src = W_dt;  N = 1024; dhi = g_w3hi; dlo = g_w3lo; ldk = 1024; ro = 0; }
    else if (bid < 2080) { bid -= 2048; src = W_x;   N = 32;   dhi = g_w3hi; dlo = g_w3lo; ldk = 1024; ro = 1024; }
    else if (bid < 2592) { bid -= 2080; src = W_out; N = 512;  dhi = g_w4hi; dlo = g_w4lo; ldk = 1024; ro = 0; }
    else if (bid < 2976) {                  // S5: zpad
        int idx = (bid - 2592) * 256 + tid;
        size_t o = (size_t)1056 * DI + idx;
        g_w3hi[o] = __float2bfloat16(0.f);
        g_w3lo[o] = __float2bfloat16(0.f);
        return;
    } else {                                // S6: bias
        int idx = (bid - 2976) * 256 + tid;
        if (idx < NC2) g_bc[idx] = (idx < DI) ? b_dt[idx] : 0.f;
        return;
    }

    // transpose+split segment
    const int ntx = N >> 5;
    const int bx  = bid % ntx, by = bid / ntx;
    const int k0  = by * 32, n0 = bx * 32;
    const int tx  = tid & 31, ty = tid >> 5;
    #pragma unroll
    for (int r = ty; r < 32; r += 8)
        t[r][tx] = src[(size_t)(k0 + r) * N + n0 + tx];
    __syncthreads();
    #pragma unroll
    for (int r = ty; r < 32; r += 8) {
        float v = t[tx][r];
        size_t o = (size_t)(ro + n0 + r) * ldk + k0 + tx;
        split32(v, &dhi[o], &dlo[o]);
    }
}

// ---------------------------------------------------------------------------
// depthwise causal conv + bias + SiLU -> g_xc (fp32 + bf16 hi/lo),
// gate = silu(res) -> g_gate
// ---------------------------------------------------------------------------
__global__ void conv_silu_kernel(const float* __restrict__ conv_w,
                                 const float* __restrict__ conv_b)
{
    int idx = blockIdx.x * 256 + threadIdx.x;
    int i = idx & (DI - 1);
    int m = idx >> 10;
    int l = m & (NL - 1);

    float4 w = ((const float4*)conv_w)[i];
    float acc = conv_b[i];
    if (l >= 3) acc = fmaf(w.x, g_xr[(size_t)(m - 3) * 2048 + i], acc);
    if (l >= 2) acc = fmaf(w.y, g_xr[(size_t)(m - 2) * 2048 + i], acc);
    if (l >= 1) acc = fmaf(w.z, g_xr[(size_t)(m - 1) * 2048 + i], acc);
    acc = fmaf(w.w, g_xr[(size_t)m * 2048 + i], acc);

    float sig = 1.f / (1.f + __expf(-acc));
    float xc = acc * sig;
    g_xc[idx] = xc;
    split32(xc, &g_xchi[idx], &g_xclo[idx]);

    float resv = g_xr[(size_t)m * 2048 + 1024 + i];
    float rsig = 1.f / (1.f + __expf(-resv));
    g_gate[idx] = resv * rsig;
}

// ---------------------------------------------------------------------------
// Chunked selective scan.
//   PASS 0: per-chunk scan from h=0; store h_local and A_prod.
//   PASS 1: reconstruct h_in inline (combine of prior chunks), re-scan chunk,
//           emit y (+D-skip, gate) as bf16 hi/lo.
// Block = (batch, 16-channel tile, chunk); grid = 4*64*8 = 2048.
// ---------------------------------------------------------------------------
template<int PASS>
__global__ __launch_bounds__(256)
void scan_pass_kernel(const float* __restrict__ A_log,
                      const float* __restrict__ D_skip)
{
    __shared__ float u_s [2][TQ][16];
    __shared__ float d_s [2][TQ][16];
    __shared__ float bc_s[2][TQ][32];

    const int tid = threadIdx.x;
    const int c   = tid >> 4;
    const int s   = tid & 15;
    const int b     = blockIdx.x >> 9;
    const int itile = (blockIdx.x >> 3) & 63;
    const int chunk = blockIdx.x & 7;
    const int i_base = itile << 4;
    const int i   = i_base + c;
    const int mb  = b * NL + chunk * CHL;

    const float ALs = A_log[s];
    const float Dsk = D_skip[i];

    const int lc   = tid & 15;
    const int lt   = tid >> 4;
    const int bt   = tid >> 5;
    const int bcol = tid & 31;

    float ru, rd, rb0, rb1;

    #define LOAD_TILE(tile) do {                                              \
        int m_ud = mb + (tile) * TQ + lt;                                     \
        ru  = g_xc [(size_t)m_ud * DI + i_base + lc];                         \
        rd  = g_dbc[(size_t)m_ud * NC2 + i_base + lc];                        \
        int m_b0 = mb + (tile) * TQ + bt;                                     \
        rb0 = g_dbc[(size_t)m_b0 * NC2 + 1024 + bcol];                        \
        rb1 = g_dbc[(size_t)(m_b0 + 8) * NC2 + 1024 + bcol];                  \
    } while (0)

    #define STS_TILE(buf) do {                                                \
        u_s [buf][lt][lc]     = ru;                                           \
        d_s [buf][lt][lc]     = rd;                                           \
        bc_s[buf][bt][bcol]   = rb0;                                          \
        bc_s[buf][bt+8][bcol] = rb1;                                          \
    } while (0)

    LOAD_TILE(0);
    STS_TILE(0);

    const int sidx0 = b * (DI * DS) + i * DS + s;
    float h = 0.f, ap;
    if (PASS == 0) {
        ap = 1.f;
    } else {
        // inline combine: h_in = scan of (hl, ap) over chunks < chunk
        for (int ch = 0; ch < chunk; ++ch) {
            int o = ch * CHST + sidx0;
            h = fmaf(g_ap[o], h, g_hl[o]);
        }
    }
    __syncthreads();

    const unsigned fm = 0xffffffffu;
    const int NT = CHL / TQ;

    for (int tile = 0; tile < NT; ++tile) {
        const int cur = tile & 1, nxt = cur ^ 1;
        if (tile + 1 < NT) LOAD_TILE(tile + 1);

        #pragma unroll
        for (int tt = 0; tt < TQ; ++tt) {
            float u  = u_s [cur][tt][c];
            float d  = d_s [cur][tt][c];
            float Bv = bc_s[cur][tt][s];

            float a  = fminf(fmaxf(d * ALs, -5.f), 5.f);
            float dA = __expf(a);
            if (PASS == 0) ap *= dA;
            h = fmaf(dA, h, d * Bv * u);

            if (PASS == 1) {
                float Cv = bc_s[cur][tt][16 + s];
                float p = h * Cv;
                p += __shfl_xor_sync(fm, p, 1);
                p += __shfl_xor_sync(fm, p, 2);
                p += __shfl_xor_sync(fm, p, 4);
                p += __shfl_xor_sync(fm, p, 8);

                if (s == 0) {
                    int m = mb + tile * TQ + tt;
                    float gate = g_gate[(size_t)m * DI + i];
                    float v = fmaf(u, Dsk, p) * gate;
                    size_t o = (size_t)m * DI + i;
                    split32(v, &g_yghi[o], &g_yglo[o]);
                }
            }
        }

        if (tile + 1 < NT) STS_TILE(nxt);
        __syncthreads();
    }

    if (PASS == 0) {
        int o = chunk * CHST + sidx0;
        g_hl[o] = h;
        g_ap[o] = ap;
    }
    #undef LOAD_TILE
    #undef STS_TILE
}

// ---------------------------------------------------------------------------
// residual + layernorm.  one warp per row (512 cols).
// ---------------------------------------------------------------------------
__global__ __launch_bounds__(256)
void ln_kernel(const float* __restrict__ x,
               const float* __restrict__ gamma,
               const float* __restrict__ beta,
               float* __restrict__ out)
{
    const int w = threadIdx.x >> 5;
    const int lane = threadIdx.x & 31;
    const int row = blockIdx.x * 8 + w;

    const float4* orow = (const float4*)&g_o[(size_t)row * DM];
    const float4* xrow = (const float4*)&x[(size_t)row * DM];

    float vals[16];
    float sum = 0.f, sq = 0.f;
    #pragma unroll
    for (int j = 0; j < 4; ++j) {
        float4 o = orow[lane + j * 32];
        float4 xv = xrow[lane + j * 32];
        float r0 = o.x + fminf(fmaxf(xv.x, -10.f), 10.f);
        float r1 = o.y + fminf(fmaxf(xv.y, -10.f), 10.f);
        float r2 = o.z + fminf(fmaxf(xv.z, -10.f), 10.f);
        float r3 = o.w + fminf(fmaxf(xv.w, -10.f), 10.f);
        vals[j * 4 + 0] = r0; vals[j * 4 + 1] = r1;
        vals[j * 4 + 2] = r2; vals[j * 4 + 3] = r3;
        sum += r0 + r1 + r2 + r3;
        sq  += r0 * r0 + r1 * r1 + r2 * r2 + r3 * r3;
    }
    #pragma unroll
    for (int off = 16; off >= 1; off >>= 1) {
        sum += __shfl_xor_sync(0xffffffffu, sum, off);
        sq  += __shfl_xor_sync(0xffffffffu, sq,  off);
    }
    const float mean = sum * (1.f / DM);
    const float var  = sq * (1.f / DM) - mean * mean;
    const float rstd = rsqrtf(var + 1e-5f);

    #pragma unroll
    for (int j = 0; j < 4; ++j) {
        float4 gm = ((const float4*)gamma)[lane + j * 32];
        float4 bt = ((const float4*)beta)[lane + j * 32];
        float4 o;
        o.x = fmaf((vals[j*4+0] - mean) * rstd, gm.x, bt.x);
        o.y = fmaf((vals[j*4+1] - mean) * rstd, gm.y, bt.y);
        o.z = fmaf((vals[j*4+2] - mean) * rstd, gm.z, bt.z);
        o.w = fmaf((vals[j*4+3] - mean) * rstd, gm.w, bt.w);
        ((float4*)&out[(size_t)row * DM])[lane + j * 32] = o;
    }
}

// ---------------------------------------------------------------------------
extern "C" void kernel_launch(void* const* d_in, const int* in_sizes, int n_in,
                              void* d_out, int out_size)
{
    const float* x      = (const float*)d_in[0];
    const float* W_in   = (const float*)d_in[1];
    const float* conv_w = (const float*)d_in[2];
    const float* conv_b = (const float*)d_in[3];
    const float* W_x    = (const float*)d_in[4];
    const float* W_dt   = (const float*)d_in[5];
    const float* b_dt   = (const float*)d_in[6];
    const float* A_log  = (const float*)d_in[7];
    const float* D_skip = (const float*)d_in[8];
    const float* W_out  = (const float*)d_in[9];
    const float* gamma  = (const float*)d_in[10];
    const float* beta   = (const float*)d_in[11];
    float* out = (float*)d_out;

    cudaFuncSetAttribute(mmagemm_kernel<false>,
                         cudaFuncAttributeMaxDynamicSharedMemorySize, GEMM_SMEM);
    cudaFuncSetAttribute(mmagemm_kernel<true>,
                         cudaFuncAttributeMaxDynamicSharedMemorySize, GEMM_SMEM);

    void *p_xr, *p_dbc, *p_o, *p_bc;
    void *p_xhi, *p_xlo, *p_xchi, *p_xclo, *p_yghi, *p_yglo;
    void *p_w1hi, *p_w1lo, *p_w3hi, *p_w3lo, *p_w4hi, *p_w4lo;
    cudaGetSymbolAddress(&p_xr,   g_xr);
    cudaGetSymbolAddress(&p_dbc,  g_dbc);
    cudaGetSymbolAddress(&p_o,    g_o);
    cudaGetSymbolAddress(&p_bc,   g_bc);
    cudaGetSymbolAddress(&p_xhi,  g_xhi);   cudaGetSymbolAddress(&p_xlo,  g_xlo);
    cudaGetSymbolAddress(&p_xchi, g_xchi);  cudaGetSymbolAddress(&p_xclo, g_xclo);
    cudaGetSymbolAddress(&p_yghi, g_yghi);  cudaGetSymbolAddress(&p_yglo, g_yglo);
    cudaGetSymbolAddress(&p_w1hi, g_w1hi);  cudaGetSymbolAddress(&p_w1lo, g_w1lo);
    cudaGetSymbolAddress(&p_w3hi, g_w3hi);  cudaGetSymbolAddress(&p_w3lo, g_w3lo);
    cudaGetSymbolAddress(&p_w4hi, g_w4hi);  cudaGetSymbolAddress(&p_w4lo, g_w4lo);

    // fused operand prep (split x, transpose+split weights, zpad, bias)
    prep_kernel<<<PREP_BLOCKS, 256>>>(x, W_in, W_dt, W_x, W_out, b_dt);

    // G1: xr = clip(x) @ W_in   [4096 x 2048], K=512
    {
        dim3 grid(2048 / 128, M_ROWS / 128);
        mmagemm_kernel<false><<<grid, 256, GEMM_SMEM>>>(
            (const bf16*)p_xhi, (const bf16*)p_xlo,
            (const bf16*)p_w1hi, (const bf16*)p_w1lo,
            nullptr, (float*)p_xr, DM, 2048);
    }

    // conv + silu -> xc (fp32 + hi/lo), gate
    conv_silu_kernel<<<(M_ROWS * DI) / 256, 256>>>(conv_w, conv_b);

    // G3: dbc = xc @ Wcomb + bcomb   [4096 x 1152], K=1024
    {
        dim3 grid(NC2 / 128, M_ROWS / 128);
        mmagemm_kernel<true><<<grid, 256, GEMM_SMEM>>>(
            (const bf16*)p_xchi, (const bf16*)p_xclo,
            (const bf16*)p_w3hi, (const bf16*)p_w3lo,
            (const float*)p_bc, (float*)p_dbc, DI, NC2);
    }

    // chunked selective scan: pass 0 (local), pass 1 (combine inline + emit)
    scan_pass_kernel<0><<<NB * 64 * NCH, 256>>>(A_log, D_skip);
    scan_pass_kernel<1><<<NB * 64 * NCH, 256>>>(A_log, D_skip);

    // G4: o = yg @ W_out   [4096 x 512], K=1024
    {
        dim3 grid(DM / 128, M_ROWS / 128);
        mmagemm_kernel<false><<<grid, 256, GEMM_SMEM>>>(
            (const bf16*)p_yghi, (const bf16*)p_yglo,
            (const bf16*)p_w4hi, (const bf16*)p_w4lo,
            nullptr, (float*)p_o, DI, DM);
    }

    // residual + layernorm -> out
    ln_kernel<<<M_ROWS / 8, 256>>>(x, gamma, beta, out);
}

// round 9
// speedup vs baseline: 1.6181x; 1.6181x over previous
#include <cuda_runtime.h>
#include <cuda_bf16.h>
#include <cstdint>

// ---------------------------------------------------------------------------
// Mamba layer. R9: 2-stage GEMM pipeline (2 CTAs/SM — the R7-fast config),
// fused prep kernel, combine folded into scan pass 1.
//   B=4, L=1024, D_MODEL=512, D_INNER=1024, D_STATE=16, D_CONV=4
// ---------------------------------------------------------------------------

typedef __nv_bfloat16 bf16;

#define NB      4
#define NL      1024
#define DM      512
#define DI      1024
#define DS      16
#define M_ROWS  (NB*NL)          // 4096
#define NC2     1152             // padded: 1024 delta | 16 B | 16 C | 96 pad
#define TQ      16               // scan tile (timesteps)
#define NCH     8                // scan chunks
#define CHL     (NL/NCH)         // 128 steps per chunk

// fp32 scratch
__device__ float g_xr  [M_ROWS * 2048];
__device__ float g_xc  [M_ROWS * DI];
__device__ float g_gate[M_ROWS * DI];
__device__ float g_dbc [M_ROWS * NC2];
__device__ float g_o   [M_ROWS * DM];
__device__ float g_bc  [NC2];

// chunked-scan state: [chunk][b][i][s] flattened
#define CHST (NB * DI * DS)      // 65536 per chunk
__device__ float g_hl [NCH * CHST];
__device__ float g_ap [NCH * CHST];

// bf16 hi/lo operand scratch
__device__ bf16 g_xhi [M_ROWS * DM],   g_xlo [M_ROWS * DM];    // clip(x)
__device__ bf16 g_xchi[M_ROWS * DI],   g_xclo[M_ROWS * DI];    // xc
__device__ bf16 g_yghi[M_ROWS * DI],   g_yglo[M_ROWS * DI];    // yg
__device__ bf16 g_w1hi[2048 * DM],     g_w1lo[2048 * DM];      // W_in^T  [2048,512]
__device__ bf16 g_w3hi[NC2 * DI],      g_w3lo[NC2 * DI];       // Wcomb^T [1152,1024]
__device__ bf16 g_w4hi[DM * DI],       g_w4lo[DM * DI];        // W_out^T [512,1024]

// ---------------------------------------------------------------------------
// helpers
// ---------------------------------------------------------------------------
__device__ __forceinline__ uint32_t s2u(const void* p) {
    uint32_t a;
    asm("{ .reg .u64 t; cvta.to.shared.u64 t, %1; cvt.u32.u64 %0, t; }"
        : "=r"(a) : "l"(p));
    return a;
}

__device__ __forceinline__ void cp16(uint32_t dst, const void* src) {
    asm volatile("cp.async.cg.shared.global [%0], [%1], 16;"
                 :: "r"(dst), "l"(src));
}
__device__ __forceinline__ void cp_commit() {
    asm volatile("cp.async.commit_group;");
}
template<int N> __device__ __forceinline__ void cp_wait() {
    asm volatile("cp.async.wait_group %0;" :: "n"(N));
}

__device__ __forceinline__ void ldmx4(uint32_t* r, uint32_t addr) {
    asm volatile("ldmatrix.sync.aligned.m8n8.x4.shared.b16 {%0,%1,%2,%3}, [%4];"
                 : "=r"(r[0]), "=r"(r[1]), "=r"(r[2]), "=r"(r[3]) : "r"(addr));
}

__device__ __forceinline__ void mma16816(float* c, const uint32_t* a,
                                         uint32_t b0, uint32_t b1) {
    asm volatile(
        "mma.sync.aligned.m16n8k16.row.col.f32.bf16.bf16.f32 "
        "{%0,%1,%2,%3}, {%4,%5,%6,%7}, {%8,%9}, {%0,%1,%2,%3};"
        : "+f"(c[0]), "+f"(c[1]), "+f"(c[2]), "+f"(c[3])
        : "r"(a[0]), "r"(a[1]), "r"(a[2]), "r"(a[3]), "r"(b0), "r"(b1));
}

__device__ __forceinline__ void split32(float v, bf16* phi, bf16* plo) {
    bf16 h = __float2bfloat16(v);
    *phi = h;
    *plo = __float2bfloat16(v - __bfloat162float(h));
}

// ---------------------------------------------------------------------------
// bf16x3 MMA GEMM: C[M,N] = A * B^T (+ bias), fp32 accumulate.
//   CTA 128x128, BK=32, 8 warps (2x4), warp tile 64x32, 2-stage cp.async
//   (81,920 B smem -> 2 CTAs/SM; cross-CTA overlap hides load latency).
//   Smem rows padded to 40 bf16 (80B): conflict-free ldmatrix.
// ---------------------------------------------------------------------------
#define APITCH      40
#define MAT_BYTES   (128 * APITCH * 2)        // 10240
#define STAGE_BYTES (4 * MAT_BYTES)           // 40960
#define GEMM_SMEM   (2 * STAGE_BYTES)         // 81920

__device__ __forceinline__ void load_mat(const bf16* __restrict__ g,
                                         int base_row, int K, int k0,
                                         uint32_t dst, int tid) {
    #pragma unroll
    for (int it = 0; it < 2; ++it) {
        int j = tid + it * 256;                 // 0..511
        int r = j >> 2;                         // 0..127
        int c = j & 3;                          // 16B chunk
        cp16(dst + r * 80 + c * 16,
             g + (size_t)(base_row + r) * K + k0 + c * 8);
    }
}

__device__ __forceinline__ void load_chunk(const bf16* __restrict__ Ahi,
                                           const bf16* __restrict__ Alo,
                                           const bf16* __restrict__ Bhi,
                                           const bf16* __restrict__ Blo,
                                           int row0, int col0, int K, int k0,
                                           uint32_t st, int tid) {
    load_mat(Ahi, row0, K, k0, st + 0*MAT_BYTES, tid);
    load_mat(Alo, row0, K, k0, st + 1*MAT_BYTES, tid);
    load_mat(Bhi, col0, K, k0, st + 2*MAT_BYTES, tid);
    load_mat(Blo, col0, K, k0, st + 3*MAT_BYTES, tid);
}

template<bool BIAS>
__global__ __launch_bounds__(256)
void mmagemm_kernel(const bf16* __restrict__ Ahi, const bf16* __restrict__ Alo,
                    const bf16* __restrict__ Bhi, const bf16* __restrict__ Blo,
                    const float* __restrict__ bias, float* __restrict__ C,
                    int K, int ldc)
{
    extern __shared__ char smem[];
    const uint32_t sb = s2u(smem);
    const int tid  = threadIdx.x;
    const int wid  = tid >> 5;
    const int lane = tid & 31;
    const int row0 = blockIdx.y * 128;
    const int col0 = blockIdx.x * 128;
    const int row_w = (wid & 1) * 64;
    const int col_w = (wid >> 1) * 32;

    float acc[4][4][4] = {};

    const int nchunk = K >> 5;

    // prologue: chunk 0 -> stage 0
    load_chunk(Ahi, Alo, Bhi, Blo, row0, col0, K, 0, sb, tid);
    cp_commit();

    const int lrow = lane & 15;
    const int lhal = (lane >> 4) & 1;

    for (int i = 0; i < nchunk; ++i) {
        const uint32_t st = sb + (uint32_t)(i & 1) * STAGE_BYTES;
        if (i + 1 < nchunk) {
            load_chunk(Ahi, Alo, Bhi, Blo, row0, col0, K, (i + 1) * 32,
                       sb + (uint32_t)((i + 1) & 1) * STAGE_BYTES, tid);
            cp_commit();
            cp_wait<1>();
        } else {
            cp_wait<0>();
        }
        __syncthreads();

        #pragma unroll
        for (int ks = 0; ks < 2; ++ks) {
            uint32_t ah[4][4], al[4][4], bh[2][4], bl[2][4];
            const uint32_t koff = ks * 32 + lhal * 16;
            #pragma unroll
            for (int mb = 0; mb < 4; ++mb) {
                const uint32_t ra = (row_w + mb * 16 + lrow) * 80 + koff;
                ldmx4(ah[mb], st + 0*MAT_BYTES + ra);
                ldmx4(al[mb], st + 1*MAT_BYTES + ra);
            }
            #pragma unroll
            for (int nb2 = 0; nb2 < 2; ++nb2) {
                const uint32_t rb = (col_w + nb2 * 16 + lrow) * 80 + koff;
                ldmx4(bh[nb2], st + 2*MAT_BYTES + rb);
                ldmx4(bl[nb2], st + 3*MAT_BYTES + rb);
            }
            #pragma unroll
            for (int mb = 0; mb < 4; ++mb) {
                #pragma unroll
                for (int nb2 = 0; nb2 < 2; ++nb2) {
                    #pragma unroll
                    for (int hf = 0; hf < 2; ++hf) {
                        float* c = acc[mb][nb2 * 2 + hf];
                        mma16816(c, ah[mb], bh[nb2][hf], bh[nb2][hf + 2]);
                        mma16816(c, ah[mb], bl[nb2][hf], bl[nb2][hf + 2]);
                        mma16816(c, al[mb], bh[nb2][hf], bh[nb2][hf + 2]);
                    }
                }
            }
        }
        __syncthreads();
    }

    const int g   = lane >> 2;
    const int tig = lane & 3;
    #pragma unroll
    for (int mb = 0; mb < 4; ++mb) {
        #pragma unroll
        for (int nb = 0; nb < 4; ++nb) {
            const int col = col0 + col_w + nb * 8 + tig * 2;
            const int r0  = row0 + row_w + mb * 16 + g;
            float* c = acc[mb][nb];
            float2 v0 = make_float2(c[0], c[1]);
            float2 v1 = make_float2(c[2], c[3]);
            if (BIAS) {
                const float b0 = bias[col], b1 = bias[col + 1];
                v0.x += b0; v0.y += b1;
                v1.x += b0; v1.y += b1;
            }
            *(float2*)&C[(size_t)r0 * ldc + col]       = v0;
            *(float2*)&C[(size_t)(r0 + 8) * ldc + col] = v1;
        }
    }
}

// ---------------------------------------------------------------------------
// fused prep kernel: one launch, segmented grid; all segments run in parallel.
// ---------------------------------------------------------------------------
#define PREP_BLOCKS (8192 + 1024 + 1024 + 32 + 512 + 384 + 5)

__global__ __launch_bounds__(256)
void prep_kernel(const float* __restrict__ x,
                 const float* __restrict__ W_in,
                 const float* __restrict__ W_dt,
                 const float* __restrict__ W_x,
                 const float* __restrict__ W_out,
                 const float* __restrict__ b_dt)
{
    __shared__ float t[32][33];
    int bid = blockIdx.x;
    const int tid = threadIdx.x;

    if (bid < 8192) {                       // S0: split x
        int idx = bid * 256 + tid;
        float v = fminf(fmaxf(x[idx], -10.f), 10.f);
        split32(v, &g_xhi[idx], &g_xlo[idx]);
        return;
    }
    bid -= 8192;

    const float* src; bf16 *dhi, *dlo;
    int N, ldk, ro;
    if (bid < 1024)      { src = W_in;  N = 2048; dhi = g_w1hi; dlo = g_w1lo; ldk = 512;  ro = 0; }
    else if (bid < 2048) { bid -= 1024; src = W_dt;  N = 1024; dhi = g_w3hi; dlo = g_w3lo; ldk = 1024; ro = 0; }
    else if (bid < 2080) { bid -= 2048; src = W_x;   N = 32;   dhi = g_w3hi; dlo = g_w3lo; ldk = 1024; ro = 1024; }
    else if (bid < 2592) { bid -= 2080; src = W_out; N = 512;  dhi = g_w4hi; dlo = g_w4lo; ldk = 1024; ro = 0; }
    else if (bid < 2976) {                  // S5: zpad
        int idx = (bid - 2592) * 256 + tid;
        size_t o = (size_t)1056 * DI + idx;
        g_w3hi[o] = __float2bfloat16(0.f);
        g_w3lo[o] = __float2bfloat16(0.f);
        return;
    } else {                                // S6: bias
        int idx = (bid - 2976) * 256 + tid;
        if (idx < NC2) g_bc[idx] = (idx < DI) ? b_dt[idx] : 0.f;
        return;
    }

    const int ntx = N >> 5;
    const int bx  = bid % ntx, by = bid / ntx;
    const int k0  = by * 32, n0 = bx * 32;
    const int tx  = tid & 31, ty = tid >> 5;
    #pragma unroll
    for (int r = ty; r < 32; r += 8)
        t[r][tx] = src[(size_t)(k0 + r) * N + n0 + tx];
    __syncthreads();
    #pragma unroll
    for (int r = ty; r < 32; r += 8) {
        float v = t[tx][r];
        size_t o = (size_t)(ro + n0 + r) * ldk + k0 + tx;
        split32(v, &dhi[o], &dlo[o]);
    }
}

// ---------------------------------------------------------------------------
// depthwise causal conv + bias + SiLU -> g_xc (fp32 + bf16 hi/lo),
// gate = silu(res) -> g_gate
// ---------------------------------------------------------------------------
__global__ void conv_silu_kernel(const float* __restrict__ conv_w,
                                 const float* __restrict__ conv_b)
{
    int idx = blockIdx.x * 256 + threadIdx.x;
    int i = idx & (DI - 1);
    int m = idx >> 10;
    int l = m & (NL - 1);

    float4 w = ((const float4*)conv_w)[i];
    float acc = conv_b[i];
    if (l >= 3) acc = fmaf(w.x, g_xr[(size_t)(m - 3) * 2048 + i], acc);
    if (l >= 2) acc = fmaf(w.y, g_xr[(size_t)(m - 2) * 2048 + i], acc);
    if (l >= 1) acc = fmaf(w.z, g_xr[(size_t)(m - 1) * 2048 + i], acc);
    acc = fmaf(w.w, g_xr[(size_t)m * 2048 + i], acc);

    float sig = 1.f / (1.f + __expf(-acc));
    float xc = acc * sig;
    g_xc[idx] = xc;
    split32(xc, &g_xchi[idx], &g_xclo[idx]);

    float resv = g_xr[(size_t)m * 2048 + 1024 + i];
    float rsig = 1.f / (1.f + __expf(-resv));
    g_gate[idx] = resv * rsig;
}

// ---------------------------------------------------------------------------
// Chunked selective scan (pass 0: local scans; pass 1: inline combine + emit).
// Block = (batch, 16-channel tile, chunk); grid = 4*64*8 = 2048.
// ---------------------------------------------------------------------------
template<int PASS>
__global__ __launch_bounds__(256)
void scan_pass_kernel(const float* __restrict__ A_log,
                      const float* __restrict__ D_skip)
{
    __shared__ float u_s [2][TQ][16];
    __shared__ float d_s [2][TQ][16];
    __shared__ float bc_s[2][TQ][32];

    const int tid = threadIdx.x;
    const int c   = tid >> 4;
    const int s   = tid & 15;
    const int b     = blockIdx.x >> 9;
    const int itile = (blockIdx.x >> 3) & 63;
    const int chunk = blockIdx.x & 7;
    const int i_base = itile << 4;
    const int i   = i_base + c;
    const int mb  = b * NL + chunk * CHL;

    const float ALs = A_log[s];
    const float Dsk = D_skip[i];

    const int lc   = tid & 15;
    const int lt   = tid >> 4;
    const int bt   = tid >> 5;
    const int bcol = tid & 31;

    float ru, rd, rb0, rb1;

    #define LOAD_TILE(tile) do {                                              \
        int m_ud = mb + (tile) * TQ + lt;                                     \
        ru  = g_xc [(size_t)m_ud * DI + i_base + lc];                         \
        rd  = g_dbc[(size_t)m_ud * NC2 + i_base + lc];                        \
        int m_b0 = mb + (tile) * TQ + bt;                                     \
        rb0 = g_dbc[(size_t)m_b0 * NC2 + 1024 + bcol];                        \
        rb1 = g_dbc[(size_t)(m_b0 + 8) * NC2 + 1024 + bcol];                  \
    } while (0)

    #define STS_TILE(buf) do {                                                \
        u_s [buf][lt][lc]     = ru;                                           \
        d_s [buf][lt][lc]     = rd;                                           \
        bc_s[buf][bt][bcol]   = rb0;                                          \
        bc_s[buf][bt+8][bcol] = rb1;                                          \
    } while (0)

    LOAD_TILE(0);
    STS_TILE(0);

    const int sidx0 = b * (DI * DS) + i * DS + s;
    float h = 0.f, ap;
    if (PASS == 0) {
        ap = 1.f;
    } else {
        for (int ch = 0; ch < chunk; ++ch) {
            int o = ch * CHST + sidx0;
            h = fmaf(g_ap[o], h, g_hl[o]);
        }
    }
    __syncthreads();

    const unsigned fm = 0xffffffffu;
    const int NT = CHL / TQ;

    for (int tile = 0; tile < NT; ++tile) {
        const int cur = tile & 1, nxt = cur ^ 1;
        if (tile + 1 < NT) LOAD_TILE(tile + 1);

        #pragma unroll
        for (int tt = 0; tt < TQ; ++tt) {
            float u  = u_s [cur][tt][c];
            float d  = d_s [cur][tt][c];
            float Bv = bc_s[cur][tt][s];

            float a  = fminf(fmaxf(d * ALs, -5.f), 5.f);
            float dA = __expf(a);
            if (PASS == 0) ap *= dA;
            h = fmaf(dA, h, d * Bv * u);

            if (PASS == 1) {
                float Cv = bc_s[cur][tt][16 + s];
                float p = h * Cv;
                p += __shfl_xor_sync(fm, p, 1);
                p += __shfl_xor_sync(fm, p, 2);
                p += __shfl_xor_sync(fm, p, 4);
                p += __shfl_xor_sync(fm, p, 8);

                if (s == 0) {
                    int m = mb + tile * TQ + tt;
                    float gate = g_gate[(size_t)m * DI + i];
                    float v = fmaf(u, Dsk, p) * gate;
                    size_t o = (size_t)m * DI + i;
                    split32(v, &g_yghi[o], &g_yglo[o]);
                }
            }
        }

        if (tile + 1 < NT) STS_TILE(nxt);
        __syncthreads();
    }

    if (PASS == 0) {
        int o = chunk * CHST + sidx0;
        g_hl[o] = h;
        g_ap[o] = ap;
    }
    #undef LOAD_TILE
    #undef STS_TILE
}

// ---------------------------------------------------------------------------
// residual + layernorm.  one warp per row (512 cols).
// ---------------------------------------------------------------------------
__global__ __launch_bounds__(256)
void ln_kernel(const float* __restrict__ x,
               const float* __restrict__ gamma,
               const float* __restrict__ beta,
               float* __restrict__ out)
{
    const int w = threadIdx.x >> 5;
    const int lane = threadIdx.x & 31;
    const int row = blockIdx.x * 8 + w;

    const float4* orow = (const float4*)&g_o[(size_t)row * DM];
    const float4* xrow = (const float4*)&x[(size_t)row * DM];

    float vals[16];
    float sum = 0.f, sq = 0.f;
    #pragma unroll
    for (int j = 0; j < 4; ++j) {
        float4 o = orow[lane + j * 32];
        float4 xv = xrow[lane + j * 32];
        float r0 = o.x + fminf(fmaxf(xv.x, -10.f), 10.f);
        float r1 = o.y + fminf(fmaxf(xv.y, -10.f), 10.f);
        float r2 = o.z + fminf(fmaxf(xv.z, -10.f), 10.f);
        float r3 = o.w + fminf(fmaxf(xv.w, -10.f), 10.f);
        vals[j * 4 + 0] = r0; vals[j * 4 + 1] = r1;
        vals[j * 4 + 2] = r2; vals[j * 4 + 3] = r3;
        sum += r0 + r1 + r2 + r3;
        sq  += r0 * r0 + r1 * r1 + r2 * r2 + r3 * r3;
    }
    #pragma unroll
    for (int off = 16; off >= 1; off >>= 1) {
        sum += __shfl_xor_sync(0xffffffffu, sum, off);
        sq  += __shfl_xor_sync(0xffffffffu, sq,  off);
    }
    const float mean = sum * (1.f / DM);
    const float var  = sq * (1.f / DM) - mean * mean;
    const float rstd = rsqrtf(var + 1e-5f);

    #pragma unroll
    for (int j = 0; j < 4; ++j) {
        float4 gm = ((const float4*)gamma)[lane + j * 32];
        float4 bt = ((const float4*)beta)[lane + j * 32];
        float4 o;
        o.x = fmaf((vals[j*4+0] - mean) * rstd, gm.x, bt.x);
        o.y = fmaf((vals[j*4+1] - mean) * rstd, gm.y, bt.y);
        o.z = fmaf((vals[j*4+2] - mean) * rstd, gm.z, bt.z);
        o.w = fmaf((vals[j*4+3] - mean) * rstd, gm.w, bt.w);
        ((float4*)&out[(size_t)row * DM])[lane + j * 32] = o;
    }
}

// ---------------------------------------------------------------------------
extern "C" void kernel_launch(void* const* d_in, const int* in_sizes, int n_in,
                              void* d_out, int out_size)
{
    const float* x      = (const float*)d_in[0];
    const float* W_in   = (const float*)d_in[1];
    const float* conv_w = (const float*)d_in[2];
    const float* conv_b = (const float*)d_in[3];
    const float* W_x    = (const float*)d_in[4];
    const float* W_dt   = (const float*)d_in[5];
    const float* b_dt   = (const float*)d_in[6];
    const float* A_log  = (const float*)d_in[7];
    const float* D_skip = (const float*)d_in[8];
    const float* W_out  = (const float*)d_in[9];
    const float* gamma  = (const float*)d_in[10];
    const float* beta   = (const float*)d_in[11];
    float* out = (float*)d_out;

    cudaFuncSetAttribute(mmagemm_kernel<false>,
                         cudaFuncAttributeMaxDynamicSharedMemorySize, GEMM_SMEM);
    cudaFuncSetAttribute(mmagemm_kernel<true>,
                         cudaFuncAttributeMaxDynamicSharedMemorySize, GEMM_SMEM);

    void *p_xr, *p_dbc, *p_o, *p_bc;
    void *p_xhi, *p_xlo, *p_xchi, *p_xclo, *p_yghi, *p_yglo;
    void *p_w1hi, *p_w1lo, *p_w3hi, *p_w3lo, *p_w4hi, *p_w4lo;
    cudaGetSymbolAddress(&p_xr,   g_xr);
    cudaGetSymbolAddress(&p_dbc,  g_dbc);
    cudaGetSymbolAddress(&p_o,    g_o);
    cudaGetSymbolAddress(&p_bc,   g_bc);
    cudaGetSymbolAddress(&p_xhi,  g_xhi);   cudaGetSymbolAddress(&p_xlo,  g_xlo);
    cudaGetSymbolAddress(&p_xchi, g_xchi);  cudaGetSymbolAddress(&p_xclo, g_xclo);
    cudaGetSymbolAddress(&p_yghi, g_yghi);  cudaGetSymbolAddress(&p_yglo, g_yglo);
    cudaGetSymbolAddress(&p_w1hi, g_w1hi);  cudaGetSymbolAddress(&p_w1lo, g_w1lo);
    cudaGetSymbolAddress(&p_w3hi, g_w3hi);  cudaGetSymbolAddress(&p_w3lo, g_w3lo);
    cudaGetSymbolAddress(&p_w4hi, g_w4hi);  cudaGetSymbolAddress(&p_w4lo, g_w4lo);

    // fused operand prep (split x, transpose+split weights, zpad, bias)
    prep_kernel<<<PREP_BLOCKS, 256>>>(x, W_in, W_dt, W_x, W_out, b_dt);

    // G1: xr = clip(x) @ W_in   [4096 x 2048], K=512
    {
        dim3 grid(2048 / 128, M_ROWS / 128);
        mmagemm_kernel<false><<<grid, 256, GEMM_SMEM>>>(
            (const bf16*)p_xhi, (const bf16*)p_xlo,
            (const bf16*)p_w1hi, (const bf16*)p_w1lo,
            nullptr, (float*)p_xr, DM, 2048);
    }

    // conv + silu -> xc (fp32 + hi/lo), gate
    conv_silu_kernel<<<(M_ROWS * DI) / 256, 256>>>(conv_w, conv_b);

    // G3: dbc = xc @ Wcomb + bcomb   [4096 x 1152], K=1024
    {
        dim3 grid(NC2 / 128, M_ROWS / 128);
        mmagemm_kernel<true><<<grid, 256, GEMM_SMEM>>>(
            (const bf16*)p_xchi, (const bf16*)p_xclo,
            (const bf16*)p_w3hi, (const bf16*)p_w3lo,
            (const float*)p_bc, (float*)p_dbc, DI, NC2);
    }

    // chunked selective scan: pass 0 (local), pass 1 (combine inline + emit)
    scan_pass_kernel<0><<<NB * 64 * NCH, 256>>>(A_log, D_skip);
    scan_pass_kernel<1><<<NB * 64 * NCH, 256>>>(A_log, D_skip);

    // G4: o = yg @ W_out   [4096 x 512], K=1024
    {
        dim3 grid(DM / 128, M_ROWS / 128);
        mmagemm_kernel<false><<<grid, 256, GEMM_SMEM>>>(
            (const bf16*)p_yghi, (const bf16*)p_yglo,
            (const bf16*)p_w4hi, (const bf16*)p_w4lo,
            nullptr, (float*)p_o, DI, DM);
    }

    // residual + layernorm -> out
    ln_kernel<<<M_ROWS / 8, 256>>>(x, gamma, beta, out);
}